// round 2
// baseline (speedup 1.0000x reference)
#include <cuda_runtime.h>
#include <math_constants.h>

// ChamferDistanceLoss: B=8, N=4096, D=3.
// loss = mean_b[ mean_i min_j d(p1_i,p2_j) + mean_j min_i d(p1_i,p2_j) ]
//      = (sum of all 65536 per-point min distances) / 32768
//
// d(p,q) = |p|^2 + |q|^2 - 2 p.q  -> per pair: 3 FFMA + 1 FMNMX
// (query norm folded in after the min: min_j(d) = qn + min_j(cn - 2 dot))

#define NPTS 4096
#define BATCH 8
#define TOTAL_PTS (BATCH * NPTS)            // 32768 per set
#define MAIN_BLOCKS 256                     // 2 dir * 8 batch * 16 qtiles
#define MAIN_THREADS 128
#define QPT 2                               // queries per thread
#define QTILE (MAIN_THREADS * QPT)          // 256 queries per block
#define CTILE 512                           // candidates staged in smem per step

// Scratch (no allocations allowed): preprocessed point tables + partial sums.
__device__ float4 g_pre1[TOTAL_PTS];
__device__ float4 g_pre2[TOTAL_PTS];
__device__ float  g_partial[MAIN_BLOCKS];

// ---------------------------------------------------------------------------
// 1) Preprocess: (x, y, z) -> (x, y, z, |p|^2)
// ---------------------------------------------------------------------------
__global__ void chamfer_prep_kernel(const float* __restrict__ p1,
                                    const float* __restrict__ p2) {
    int i = blockIdx.x * blockDim.x + threadIdx.x;   // 0 .. 65535
    if (i >= 2 * TOTAL_PTS) return;
    const float* src = (i < TOTAL_PTS) ? p1 : p2;
    float4* dst      = (i < TOTAL_PTS) ? g_pre1 : g_pre2;
    int k = i & (TOTAL_PTS - 1);
    float x = src[3 * k + 0];
    float y = src[3 * k + 1];
    float z = src[3 * k + 2];
    float n = fmaf(x, x, fmaf(y, y, z * z));
    dst[k] = make_float4(x, y, z, n);
}

// ---------------------------------------------------------------------------
// 2) Main: each block = (dir, batch, query-tile of 256).
//    Candidates streamed through smem as (-2x, -2y, -2z, |c|^2).
// ---------------------------------------------------------------------------
__global__ void __launch_bounds__(MAIN_THREADS, 2)
chamfer_main_kernel() {
    __shared__ float4 sc[CTILE];
    __shared__ float  wsum[MAIN_THREADS / 32];

    int bx  = blockIdx.x;
    int dir = bx & 1;
    int b   = (bx >> 1) & 7;
    int qt  = bx >> 4;                 // 0..15

    const float4* __restrict__ qsrc = (dir == 0) ? g_pre1 : g_pre2;
    const float4* __restrict__ csrc = (dir == 0) ? g_pre2 : g_pre1;
    qsrc += b * NPTS;
    csrc += b * NPTS;

    int t = threadIdx.x;
    int qbase = qt * QTILE;

    float4 q0 = qsrc[qbase + t];
    float4 q1 = qsrc[qbase + MAIN_THREADS + t];

    float m0 = CUDART_INF_F;
    float m1 = CUDART_INF_F;

    for (int ct = 0; ct < NPTS; ct += CTILE) {
        // Stage CTILE candidates: premultiply by -2, keep |c|^2.
        #pragma unroll
        for (int j = 0; j < CTILE / MAIN_THREADS; ++j) {
            int idx = t + j * MAIN_THREADS;
            float4 c = csrc[ct + idx];
            sc[idx] = make_float4(-2.0f * c.x, -2.0f * c.y, -2.0f * c.z, c.w);
        }
        __syncthreads();

        #pragma unroll 8
        for (int j = 0; j < CTILE; ++j) {
            float4 c = sc[j];                       // broadcast LDS.128
            float d0 = fmaf(c.x, q0.x, fmaf(c.y, q0.y, fmaf(c.z, q0.z, c.w)));
            float d1 = fmaf(c.x, q1.x, fmaf(c.y, q1.y, fmaf(c.z, q1.z, c.w)));
            m0 = fminf(m0, d0);
            m1 = fminf(m1, d1);
        }
        __syncthreads();
    }

    // Per-thread contribution: (qn + min) for each owned query.
    float s = (q0.w + m0) + (q1.w + m1);

    // Deterministic block reduction.
    #pragma unroll
    for (int off = 16; off > 0; off >>= 1)
        s += __shfl_down_sync(0xffffffffu, s, off);
    if ((t & 31) == 0) wsum[t >> 5] = s;
    __syncthreads();
    if (t == 0) {
        float p = 0.0f;
        #pragma unroll
        for (int w = 0; w < MAIN_THREADS / 32; ++w) p += wsum[w];
        g_partial[bx] = p;
    }
}

// ---------------------------------------------------------------------------
// 3) Final: deterministic sum of 256 partials -> loss scalar.
// ---------------------------------------------------------------------------
__global__ void chamfer_final_kernel(float* __restrict__ out) {
    __shared__ float wsum[MAIN_BLOCKS / 32];
    int t = threadIdx.x;
    float s = g_partial[t];
    #pragma unroll
    for (int off = 16; off > 0; off >>= 1)
        s += __shfl_down_sync(0xffffffffu, s, off);
    if ((t & 31) == 0) wsum[t >> 5] = s;
    __syncthreads();
    if (t == 0) {
        float tot = 0.0f;
        #pragma unroll
        for (int w = 0; w < MAIN_BLOCKS / 32; ++w) tot += wsum[w];
        out[0] = tot * (1.0f / (float)(BATCH * NPTS));
    }
}

extern "C" void kernel_launch(void* const* d_in, const int* in_sizes, int n_in,
                              void* d_out, int out_size) {
    const float* p1 = (const float*)d_in[0];
    const float* p2 = (const float*)d_in[1];
    float* out = (float*)d_out;

    chamfer_prep_kernel<<<(2 * TOTAL_PTS + 255) / 256, 256>>>(p1, p2);
    chamfer_main_kernel<<<MAIN_BLOCKS, MAIN_THREADS>>>();
    chamfer_final_kernel<<<1, MAIN_BLOCKS>>>(out);
}